// round 9
// baseline (speedup 1.0000x reference)
#include <cuda_runtime.h>
#include <cuda_fp16.h>

// CapsuleLayer dynamic routing, GB300 sm_103a.
// B=32, IN_CAPS=1152, P=64, NUM_CAPS=32, Q=64, NUM_ROUTING=3.
//
// hat[b,i,c,q] = sum_p x[b,i,p] * W[i,c,p,q]   (tf32 mma.sync, stored fp16)
// r0: c0 = softmax_c(bias) batch-independent -> S0 partials inside GEMM (fp32)
// r1: b1 = bias + <hat,v0>_q ; S1 = sum_i softmax_c(b1)*hat ; v1=squash(S1)
// r2: b2 = bias + <hat,v0+v1>_q ; S2 = ... ; out = squash(S2)

#define BB 32
#define IC 1152
#define PP 64
#define NC 32
#define QQ 64
#define HAT_ELEMS (BB * IC * NC * QQ)
#define SV (BB * NC * QQ)
#define NIBLK 36

// ---------------- device scratch ----------------
__device__ __align__(16) __half g_hat[HAT_ELEMS];      // 151 MB
__device__ __align__(16) float g_S0p[NIBLK * SV];      // 9.4 MB partials
__device__ __align__(16) float g_S1[SV];
__device__ __align__(16) float g_S2[SV];
__device__ __align__(16) float g_v0[SV];
__device__ __align__(16) float g_v01[SV];

// ---------------- helpers ----------------
__device__ __forceinline__ unsigned int fu(float f) { return __float_as_uint(f); }

__device__ __forceinline__ void cp16(const void* smem_dst, const void* gmem_src) {
    unsigned int s = (unsigned int)__cvta_generic_to_shared(smem_dst);
    asm volatile("cp.async.cg.shared.global [%0], [%1], 16;" :: "r"(s), "l"(gmem_src));
}
__device__ __forceinline__ void cp_commit() {
    asm volatile("cp.async.commit_group;");
}
template <int N>
__device__ __forceinline__ void cp_wait() {
    asm volatile("cp.async.wait_group %0;" :: "n"(N));
}

// tf32 m16n8k8: D += A*B. A row-major [16x8], B col-major [8x8], fp32 accum.
#define MMA_TF32(D, A, B0, B1)                                            \
    asm volatile(                                                          \
        "mma.sync.aligned.m16n8k8.row.col.f32.tf32.tf32.f32 "              \
        "{%0,%1,%2,%3},{%4,%5,%6,%7},{%8,%9},{%0,%1,%2,%3};"               \
        : "+f"((D)[0]), "+f"((D)[1]), "+f"((D)[2]), "+f"((D)[3])           \
        : "r"(fu((A)[0])), "r"(fu((A)[1])), "r"(fu((A)[2])), "r"(fu((A)[3])), \
          "r"(fu(B0)), "r"(fu(B1)))

// ---------------- prep ----------------
__global__ void zero_kernel() {
    int idx = blockIdx.x * blockDim.x + threadIdx.x;
    if (idx < SV) {
        g_S1[idx] = 0.f;
        g_S2[idx] = 0.f;
    }
}

// ---------------- GEMM (tf32): hat (fp16, staged) + S0 partials + fused c0 --
// Grid (16 cpairs, 36 iblocks), 128 threads (4 warps), 2 CTAs/SM.
// Per i: A = x[32b x 64p], B = W[i, 2 capsules] as [64k x 128n].
// Warp w owns n-slice n0=w*32. 8 k-steps of m16n8k8, mt2 x nt4 per warp.
#define ICH 32
#define WS_STRIDE 136     // 136 % 32 == 8 -> bank = 8k+n : conflict-free B reads
#define XS_STRIDE 68      // 68 % 32 == 4  -> bank = 4b+p : conflict-free A reads
#define HS_STRIDE 136     // halfs per staging row (= 68 words): bank = 4g+tig, CF
#define WS_FLOATS (PP * WS_STRIDE)   // 8704
#define XS_FLOATS (BB * XS_STRIDE)   // 2176
#define HS_FLOATS (BB * HS_STRIDE / 2)  // 2176 floats (32 rows x 136 halfs)
#define GEMM_SMEM_BYTES ((2 * WS_FLOATS + 2 * XS_FLOATS + HS_FLOATS) * 4)  // 95744

__device__ __forceinline__ void gemm_prefetch(float* ws, float* xs,
                                              const float* __restrict__ x,
                                              const float* __restrict__ W,
                                              int i, int cpair, int tid) {
    const float4* wsrc = (const float4*)(W + ((size_t)i * NC + cpair * 2) * (PP * QQ));
#pragma unroll
    for (int k = 0; k < 16; k++) {
        int j4 = tid + 128 * k;          // [0,2048)
        int cl = j4 >> 10;
        int p = (j4 >> 4) & 63;
        int q4 = j4 & 15;
        cp16(ws + p * WS_STRIDE + cl * QQ + q4 * 4, wsrc + j4);
    }
#pragma unroll
    for (int k = 0; k < 4; k++) {
        int j = tid + 128 * k;           // [0,512)
        int b = j >> 4;
        int p4 = j & 15;
        cp16(xs + b * XS_STRIDE + p4 * 4, x + ((size_t)b * IC + i) * PP + p4 * 4);
    }
}

__global__ __launch_bounds__(128, 2) void gemm_kernel(const float* __restrict__ x,
                                                      const float* __restrict__ W,
                                                      const float* __restrict__ bias) {
    extern __shared__ __align__(16) float smem[];
    __shared__ float c0sh[ICH][2];
    float* ws0 = smem;
    float* ws1 = smem + WS_FLOATS;
    float* xs0 = smem + 2 * WS_FLOATS;
    float* xs1 = xs0 + XS_FLOATS;
    __half* stag = (__half*)(xs1 + XS_FLOATS);   // [32 rows][136 halfs]

    int tid = threadIdx.x;
    int warp = tid >> 5;
    int lane = tid & 31;
    int g = lane >> 2;      // 0..7
    int tig = lane & 3;     // 0..3
    int cpair = blockIdx.x;
    int iblk = blockIdx.y;
    int i0 = iblk * ICH;
    int n0 = warp * 32;               // slice within 128-wide N
    int cl = warp >> 1;               // capsule-local
    int c = cpair * 2 + cl;
    int qn = n0 & 63;                 // q-base of slice within capsule
    int qbase = qn + tig * 2;

    gemm_prefetch(ws0, xs0, x, W, i0, cpair, tid);
    cp_commit();

    // fused c0 = softmax_c(bias) for this CTA's rows (overlaps first loads)
    if (tid < ICH) {
        const float* bp = bias + (size_t)(i0 + tid) * NC;
        float m = -1e30f;
#pragma unroll 8
        for (int cc = 0; cc < NC; cc++) m = fmaxf(m, bp[cc]);
        float s = 0.f;
#pragma unroll 8
        for (int cc = 0; cc < NC; cc++) s += __expf(bp[cc] - m);
        float inv = 1.f / s;
        c0sh[tid][0] = __expf(bp[cpair * 2 + 0] - m) * inv;
        c0sh[tid][1] = __expf(bp[cpair * 2 + 1] - m) * inv;
    }

    float s0[2][4][4];
#pragma unroll
    for (int mt = 0; mt < 2; mt++)
#pragma unroll
        for (int nt = 0; nt < 4; nt++)
#pragma unroll
            for (int j = 0; j < 4; j++) s0[mt][nt][j] = 0.f;

    for (int ii = 0; ii < ICH; ii++) {
        int i = i0 + ii;
        cp_wait<0>();
        __syncthreads();   // also orders prev iter's staging reads vs this STS
        if (ii + 1 < ICH) {
            float* wsn = ((ii + 1) & 1) ? ws1 : ws0;
            float* xsn = ((ii + 1) & 1) ? xs1 : xs0;
            gemm_prefetch(wsn, xsn, x, W, i + 1, cpair, tid);
        }
        cp_commit();
        const float* wsc = (ii & 1) ? ws1 : ws0;
        const float* xsc = (ii & 1) ? xs1 : xs0;

        float d[2][4][4];
#pragma unroll
        for (int mt = 0; mt < 2; mt++)
#pragma unroll
            for (int nt = 0; nt < 4; nt++)
#pragma unroll
                for (int j = 0; j < 4; j++) d[mt][nt][j] = 0.f;

#pragma unroll
        for (int ks = 0; ks < 8; ks++) {
            float a[2][4];
#pragma unroll
            for (int mt = 0; mt < 2; mt++) {
                int base = (mt * 16 + g) * XS_STRIDE + ks * 8 + tig;
                a[mt][0] = xsc[base];
                a[mt][1] = xsc[base + 8 * XS_STRIDE];
                a[mt][2] = xsc[base + 4];
                a[mt][3] = xsc[base + 8 * XS_STRIDE + 4];
            }
#pragma unroll
            for (int nt = 0; nt < 4; nt++) {
                int bb = (ks * 8 + tig) * WS_STRIDE + n0 + nt * 8 + g;
                float b0 = wsc[bb];
                float b1 = wsc[bb + 4 * WS_STRIDE];
                MMA_TF32(d[0][nt], a[0], b0, b1);
                MMA_TF32(d[1][nt], a[1], b0, b1);
            }
        }

        // S0 fused accumulation + stage hat tile in smem (conflict-free STS)
        float wgt = c0sh[ii][cl];
#pragma unroll
        for (int mt = 0; mt < 2; mt++) {
#pragma unroll
            for (int nt = 0; nt < 4; nt++) {
                int row0 = mt * 16 + g;
                int ncol = n0 + nt * 8 + tig * 2;
                *(__half2*)(stag + row0 * HS_STRIDE + ncol) =
                    __floats2half2_rn(d[mt][nt][0], d[mt][nt][1]);
                *(__half2*)(stag + (row0 + 8) * HS_STRIDE + ncol) =
                    __floats2half2_rn(d[mt][nt][2], d[mt][nt][3]);
#pragma unroll
                for (int j = 0; j < 4; j++)
                    s0[mt][nt][j] = fmaf(wgt, d[mt][nt][j], s0[mt][nt][j]);
            }
        }
        __syncthreads();

        // coalesced writeback: staging row b (n 0..127) -> 256B contiguous gmem
        // (capsules c, c+1 adjacent: ((b*IC+i)*NC + cpair*2)*QQ, 256 halfs)
        {
            int c16 = lane & 15;                 // 16B chunk within row
            int rsub = lane >> 4;                // 0..1
#pragma unroll
            for (int k = 0; k < 4; k++) {
                int r = warp * 8 + k * 2 + rsub;
                uint4 v = *(const uint4*)(stag + r * HS_STRIDE + c16 * 8);
                __half* dst = g_hat + (((size_t)r * IC + i) * NC + cpair * 2) * QQ
                              + c16 * 8;
                *(uint4*)dst = v;
            }
        }
    }

    // non-atomic per-iblock S0 partials
    float* sp = g_S0p + (size_t)iblk * SV;
#pragma unroll
    for (int mt = 0; mt < 2; mt++) {
#pragma unroll
        for (int nt = 0; nt < 4; nt++) {
            int q = qbase + nt * 8;
            int b0r = mt * 16 + g;
            *(float2*)(sp + ((size_t)b0r * NC + c) * QQ + q) =
                make_float2(s0[mt][nt][0], s0[mt][nt][1]);
            *(float2*)(sp + ((size_t)(b0r + 8) * NC + c) * QQ + q) =
                make_float2(s0[mt][nt][2], s0[mt][nt][3]);
        }
    }
}

// ---------------- routing pass (rounds 1, 2), fp16 hat, depth-2 pipeline ----
#define RICH 36

__global__ __launch_bounds__(256) void route_kernel(int round,
                                                    const float* __restrict__ bias) {
    __shared__ __align__(16) float vsh[NC * QQ];          // 8 KB
    __shared__ __align__(16) __half hb[3][NC * QQ];       // 3 x 4 KB
    __shared__ float tb[NC];
    __shared__ float bsh[RICH * NC];                      // 4.6 KB

    const float* vin = (round == 1) ? g_v0 : g_v01;
    float* Sout = (round == 1) ? g_S1 : g_S2;

    int tid = threadIdx.x;
    int lane = tid & 31;
    int warp = tid >> 5;
    int b = blockIdx.y;
    int i0 = blockIdx.x * RICH;

    for (int j = tid; j < NC * QQ; j += 256) vsh[j] = vin[b * (NC * QQ) + j];
    for (int j = tid; j < RICH * NC; j += 256) bsh[j] = bias[i0 * NC + j];

    cp16(hb[0] + tid * 8, g_hat + ((size_t)b * IC + i0) * (NC * QQ) + tid * 8);
    cp_commit();
    cp16(hb[1] + tid * 8, g_hat + ((size_t)b * IC + i0 + 1) * (NC * QQ) + tid * 8);
    cp_commit();

    float racc[8];
#pragma unroll
    for (int j = 0; j < 8; j++) racc[j] = 0.f;

    int c = tid >> 3, jj = tid & 7;
    const float2* v2 = (const float2*)vsh;

    for (int ii = 0; ii < RICH; ii++) {
        cp_wait<1>();   // tile ii ready
        __syncthreads();
        if (ii + 2 < RICH) {
            int buf = (ii + 2) % 3;
            cp16(hb[buf] + tid * 8,
                 g_hat + ((size_t)b * IC + i0 + ii + 2) * (NC * QQ) + tid * 8);
        }
        cp_commit();
        const __half2* hp = (const __half2*)hb[ii % 3];

        // logits: 8 threads per capsule
        float s = 0.f;
#pragma unroll
        for (int m = 0; m < 4; m++) {
            float2 h = __half22float2(hp[c * 32 + jj * 4 + m]);
            float2 v = v2[c * 32 + jj * 4 + m];
            s += h.x * v.x + h.y * v.y;
        }
        s += __shfl_down_sync(0xffffffffu, s, 4);
        s += __shfl_down_sync(0xffffffffu, s, 2);
        s += __shfl_down_sync(0xffffffffu, s, 1);
        if (jj == 0) tb[c] = bsh[ii * NC + c] + s;
        __syncthreads();

        // softmax, redundantly per warp
        float t = tb[lane];
        float m = t;
#pragma unroll
        for (int o = 16; o > 0; o >>= 1)
            m = fmaxf(m, __shfl_xor_sync(0xffffffffu, m, o));
        float e = __expf(t - m);
        float se = e;
#pragma unroll
        for (int o = 16; o > 0; o >>= 1)
            se += __shfl_xor_sync(0xffffffffu, se, o);
        float w = e / se;

#pragma unroll
        for (int k = 0; k < 4; k++) {
            int idx2 = tid + 256 * k;
            float wc = __shfl_sync(0xffffffffu, w, 8 * k + warp);
            float2 h = __half22float2(hp[idx2]);
            racc[2 * k] += wc * h.x;
            racc[2 * k + 1] += wc * h.y;
        }
    }

#pragma unroll
    for (int k = 0; k < 4; k++) {
        int idx2 = tid + 256 * k;
        atomicAdd(&Sout[b * (NC * QQ) + idx2 * 2], racc[2 * k]);
        atomicAdd(&Sout[b * (NC * QQ) + idx2 * 2 + 1], racc[2 * k + 1]);
    }
}

// ---------------- squash ----------------
// squash0: reduce S0 partials + squash -> v0
__global__ void squash0_kernel() {
    int vec = blockIdx.x;  // b*NC + c
    int lane = threadIdx.x;
    float x0 = 0.f, x1 = 0.f;
#pragma unroll 4
    for (int ib = 0; ib < NIBLK; ib++) {
        x0 += g_S0p[(size_t)ib * SV + vec * QQ + lane];
        x1 += g_S0p[(size_t)ib * SV + vec * QQ + 32 + lane];
    }
    float ss = x0 * x0 + x1 * x1;
#pragma unroll
    for (int o = 16; o > 0; o >>= 1)
        ss += __shfl_xor_sync(0xffffffffu, ss, o);
    float sc = (ss > 0.f) ? (ss / (1.f + ss)) * rsqrtf(ss) : 0.f;
    g_v0[vec * QQ + lane] = sc * x0;
    g_v0[vec * QQ + 32 + lane] = sc * x1;
}

// mode 1: v01 = v0 + squash(S1); mode 2: out = squash(S2)
__global__ void squash_kernel(int mode, float* __restrict__ dout) {
    const float* S = (mode == 1) ? g_S1 : g_S2;
    int vec = blockIdx.x;
    int lane = threadIdx.x;
    float x0 = S[vec * QQ + lane];
    float x1 = S[vec * QQ + 32 + lane];
    float ss = x0 * x0 + x1 * x1;
#pragma unroll
    for (int o = 16; o > 0; o >>= 1)
        ss += __shfl_xor_sync(0xffffffffu, ss, o);
    float sc = (ss > 0.f) ? (ss / (1.f + ss)) * rsqrtf(ss) : 0.f;
    float o0 = sc * x0, o1 = sc * x1;
    if (mode == 1) {
        g_v01[vec * QQ + lane] = g_v0[vec * QQ + lane] + o0;
        g_v01[vec * QQ + 32 + lane] = g_v0[vec * QQ + 32 + lane] + o1;
    } else {
        dout[vec * QQ + lane] = o0;
        dout[vec * QQ + 32 + lane] = o1;
    }
}

// ---------------- launch ----------------
extern "C" void kernel_launch(void* const* d_in, const int* in_sizes, int n_in,
                              void* d_out, int out_size) {
    const float* x = (const float*)d_in[0];     // [32,1152,64]
    const float* W = (const float*)d_in[1];     // [1152,32,64,64]
    const float* bias = (const float*)d_in[2];  // [1,1152,32,1]
    float* out = (float*)d_out;                 // [32,32,64]

    static int smem_set = 0;
    if (!smem_set) {
        cudaFuncSetAttribute(gemm_kernel, cudaFuncAttributeMaxDynamicSharedMemorySize,
                             GEMM_SMEM_BYTES);
        smem_set = 1;
    }

    zero_kernel<<<SV / 256, 256>>>();
    gemm_kernel<<<dim3(NC / 2, NIBLK), 128, GEMM_SMEM_BYTES>>>(x, W, bias);
    squash0_kernel<<<BB * NC, 32>>>();
    route_kernel<<<dim3(IC / RICH, BB), 256>>>(1, bias);
    squash_kernel<<<BB * NC, 32>>>(1, out);
    route_kernel<<<dim3(IC / RICH, BB), 256>>>(2, bias);
    squash_kernel<<<BB * NC, 32>>>(2, out);
}

// round 10
// speedup vs baseline: 1.1246x; 1.1246x over previous
#include <cuda_runtime.h>
#include <cuda_fp16.h>

// CapsuleLayer dynamic routing, GB300 sm_103a.
// B=32, IN_CAPS=1152, P=64, NUM_CAPS=32, Q=64, NUM_ROUTING=3.
//
// hat[b,i,c,q] = sum_p x[b,i,p] * W[i,c,p,q]   (tf32 mma.sync, stored fp16)
// r0: c0 = softmax_c(bias) batch-independent -> S0 partials inside GEMM (fp32)
// r1: b1 = bias + <hat,v0>_q ; S1 = sum_i softmax_c(b1)*hat ; v1=squash(S1)
// r2: b2 = bias + <hat,v0+v1>_q ; S2 = ... ; out = squash(S2)

#define BB 32
#define IC 1152
#define PP 64
#define NC 32
#define QQ 64
#define HAT_ELEMS (BB * IC * NC * QQ)
#define SV (BB * NC * QQ)
#define NIBLK 36

// ---------------- device scratch ----------------
__device__ __align__(16) __half g_hat[HAT_ELEMS];      // 151 MB
__device__ __align__(16) float g_S0p[NIBLK * SV];      // 9.4 MB partials
__device__ __align__(16) float g_S1[SV];
__device__ __align__(16) float g_S2[SV];
__device__ __align__(16) float g_v0[SV];
__device__ __align__(16) float g_v01[SV];

// ---------------- helpers ----------------
__device__ __forceinline__ unsigned int fu(float f) { return __float_as_uint(f); }

__device__ __forceinline__ void cp16(const void* smem_dst, const void* gmem_src) {
    unsigned int s = (unsigned int)__cvta_generic_to_shared(smem_dst);
    asm volatile("cp.async.cg.shared.global [%0], [%1], 16;" :: "r"(s), "l"(gmem_src));
}
__device__ __forceinline__ void cp_commit() {
    asm volatile("cp.async.commit_group;");
}
template <int N>
__device__ __forceinline__ void cp_wait() {
    asm volatile("cp.async.wait_group %0;" :: "n"(N));
}

// tf32 m16n8k8: D += A*B. A row-major [16x8], B col-major [8x8], fp32 accum.
#define MMA_TF32(D, A, B0, B1)                                            \
    asm volatile(                                                          \
        "mma.sync.aligned.m16n8k8.row.col.f32.tf32.tf32.f32 "              \
        "{%0,%1,%2,%3},{%4,%5,%6,%7},{%8,%9},{%0,%1,%2,%3};"               \
        : "+f"((D)[0]), "+f"((D)[1]), "+f"((D)[2]), "+f"((D)[3])           \
        : "r"(fu((A)[0])), "r"(fu((A)[1])), "r"(fu((A)[2])), "r"(fu((A)[3])), \
          "r"(fu(B0)), "r"(fu(B1)))

// ---------------- prep ----------------
__global__ void zero_kernel() {
    int idx = blockIdx.x * blockDim.x + threadIdx.x;
    if (idx < SV) {
        g_S1[idx] = 0.f;
        g_S2[idx] = 0.f;
    }
}

// ---------------- GEMM (tf32): hat (fp16, staged) + S0 partials + fused c0 --
// Grid (16 cpairs, 36 iblocks), 128 threads (4 warps), 2 CTAs/SM.
#define ICH 32
#define WS_STRIDE 136     // 136 % 32 == 8 -> bank = 8k+n : conflict-free B reads
#define XS_STRIDE 68      // 68 % 32 == 4  -> bank = 4b+p : conflict-free A reads
#define HS_STRIDE 136     // halfs per staging row
#define WS_FLOATS (PP * WS_STRIDE)   // 8704
#define XS_FLOATS (BB * XS_STRIDE)   // 2176
#define HS_FLOATS (BB * HS_STRIDE / 2)
#define GEMM_SMEM_BYTES ((2 * WS_FLOATS + 2 * XS_FLOATS + HS_FLOATS) * 4)  // 95744

__device__ __forceinline__ void gemm_prefetch(float* ws, float* xs,
                                              const float* __restrict__ x,
                                              const float* __restrict__ W,
                                              int i, int cpair, int tid) {
    const float4* wsrc = (const float4*)(W + ((size_t)i * NC + cpair * 2) * (PP * QQ));
#pragma unroll
    for (int k = 0; k < 16; k++) {
        int j4 = tid + 128 * k;          // [0,2048)
        int cl = j4 >> 10;
        int p = (j4 >> 4) & 63;
        int q4 = j4 & 15;
        cp16(ws + p * WS_STRIDE + cl * QQ + q4 * 4, wsrc + j4);
    }
#pragma unroll
    for (int k = 0; k < 4; k++) {
        int j = tid + 128 * k;           // [0,512)
        int b = j >> 4;
        int p4 = j & 15;
        cp16(xs + b * XS_STRIDE + p4 * 4, x + ((size_t)b * IC + i) * PP + p4 * 4);
    }
}

__global__ __launch_bounds__(128, 2) void gemm_kernel(const float* __restrict__ x,
                                                      const float* __restrict__ W,
                                                      const float* __restrict__ bias) {
    extern __shared__ __align__(16) float smem[];
    __shared__ float c0sh[ICH][2];
    float* ws0 = smem;
    float* ws1 = smem + WS_FLOATS;
    float* xs0 = smem + 2 * WS_FLOATS;
    float* xs1 = xs0 + XS_FLOATS;
    __half* stag = (__half*)(xs1 + XS_FLOATS);   // [32 rows][136 halfs]

    int tid = threadIdx.x;
    int warp = tid >> 5;
    int lane = tid & 31;
    int g = lane >> 2;      // 0..7
    int tig = lane & 3;     // 0..3
    int cpair = blockIdx.x;
    int iblk = blockIdx.y;
    int i0 = iblk * ICH;
    int n0 = warp * 32;               // slice within 128-wide N
    int cl = warp >> 1;               // capsule-local
    int c = cpair * 2 + cl;
    int qn = n0 & 63;
    int qbase = qn + tig * 2;

    gemm_prefetch(ws0, xs0, x, W, i0, cpair, tid);
    cp_commit();

    // fused c0 = softmax_c(bias) for this CTA's rows (overlaps first loads)
    if (tid < ICH) {
        const float* bp = bias + (size_t)(i0 + tid) * NC;
        float m = -1e30f;
#pragma unroll 8
        for (int cc = 0; cc < NC; cc++) m = fmaxf(m, bp[cc]);
        float s = 0.f;
#pragma unroll 8
        for (int cc = 0; cc < NC; cc++) s += __expf(bp[cc] - m);
        float inv = 1.f / s;
        c0sh[tid][0] = __expf(bp[cpair * 2 + 0] - m) * inv;
        c0sh[tid][1] = __expf(bp[cpair * 2 + 1] - m) * inv;
    }

    float s0[2][4][4];
#pragma unroll
    for (int mt = 0; mt < 2; mt++)
#pragma unroll
        for (int nt = 0; nt < 4; nt++)
#pragma unroll
            for (int j = 0; j < 4; j++) s0[mt][nt][j] = 0.f;

    for (int ii = 0; ii < ICH; ii++) {
        int i = i0 + ii;
        cp_wait<0>();
        __syncthreads();
        if (ii + 1 < ICH) {
            float* wsn = ((ii + 1) & 1) ? ws1 : ws0;
            float* xsn = ((ii + 1) & 1) ? xs1 : xs0;
            gemm_prefetch(wsn, xsn, x, W, i + 1, cpair, tid);
        }
        cp_commit();
        const float* wsc = (ii & 1) ? ws1 : ws0;
        const float* xsc = (ii & 1) ? xs1 : xs0;

        float d[2][4][4];
#pragma unroll
        for (int mt = 0; mt < 2; mt++)
#pragma unroll
            for (int nt = 0; nt < 4; nt++)
#pragma unroll
                for (int j = 0; j < 4; j++) d[mt][nt][j] = 0.f;

#pragma unroll
        for (int ks = 0; ks < 8; ks++) {
            float a[2][4];
#pragma unroll
            for (int mt = 0; mt < 2; mt++) {
                int base = (mt * 16 + g) * XS_STRIDE + ks * 8 + tig;
                a[mt][0] = xsc[base];
                a[mt][1] = xsc[base + 8 * XS_STRIDE];
                a[mt][2] = xsc[base + 4];
                a[mt][3] = xsc[base + 8 * XS_STRIDE + 4];
            }
#pragma unroll
            for (int nt = 0; nt < 4; nt++) {
                int bb = (ks * 8 + tig) * WS_STRIDE + n0 + nt * 8 + g;
                float b0 = wsc[bb];
                float b1 = wsc[bb + 4 * WS_STRIDE];
                MMA_TF32(d[0][nt], a[0], b0, b1);
                MMA_TF32(d[1][nt], a[1], b0, b1);
            }
        }

        // S0 fused accumulation + stage hat tile in smem (conflict-free STS)
        float wgt = c0sh[ii][cl];
#pragma unroll
        for (int mt = 0; mt < 2; mt++) {
#pragma unroll
            for (int nt = 0; nt < 4; nt++) {
                int row0 = mt * 16 + g;
                int ncol = n0 + nt * 8 + tig * 2;
                *(__half2*)(stag + row0 * HS_STRIDE + ncol) =
                    __floats2half2_rn(d[mt][nt][0], d[mt][nt][1]);
                *(__half2*)(stag + (row0 + 8) * HS_STRIDE + ncol) =
                    __floats2half2_rn(d[mt][nt][2], d[mt][nt][3]);
#pragma unroll
                for (int j = 0; j < 4; j++)
                    s0[mt][nt][j] = fmaf(wgt, d[mt][nt][j], s0[mt][nt][j]);
            }
        }
        __syncthreads();

        // coalesced writeback: staging row b (n 0..127) -> 256B contiguous gmem
        {
            int c16 = lane & 15;
            int rsub = lane >> 4;
#pragma unroll
            for (int k = 0; k < 4; k++) {
                int r = warp * 8 + k * 2 + rsub;
                uint4 v = *(const uint4*)(stag + r * HS_STRIDE + c16 * 8);
                __half* dst = g_hat + (((size_t)r * IC + i) * NC + cpair * 2) * QQ
                              + c16 * 8;
                *(uint4*)dst = v;
            }
        }
    }

    // non-atomic per-iblock S0 partials
    float* sp = g_S0p + (size_t)iblk * SV;
#pragma unroll
    for (int mt = 0; mt < 2; mt++) {
#pragma unroll
        for (int nt = 0; nt < 4; nt++) {
            int q = qbase + nt * 8;
            int b0r = mt * 16 + g;
            *(float2*)(sp + ((size_t)b0r * NC + c) * QQ + q) =
                make_float2(s0[mt][nt][0], s0[mt][nt][1]);
            *(float2*)(sp + ((size_t)(b0r + 8) * NC + c) * QQ + q) =
                make_float2(s0[mt][nt][2], s0[mt][nt][3]);
        }
    }
}

// ---------------- routing pass (rounds 1, 2) -------------------------------
// Register-resident rewrite: thread (c=tid>>3, jj=tid&7) owns hat elements
// [c*64 + jj*8, +8). v slice preloaded to registers; hat tile read ONCE per
// iter as LDS.128 and reused for logits + accumulation; softmax weight via
// a single shuffle. L1 wavefronts/warp/iter ~6 (was ~16).
#define RICH 36

__global__ __launch_bounds__(256) void route_kernel(int round,
                                                    const float* __restrict__ bias) {
    __shared__ __align__(16) __half hb[3][NC * QQ];       // 3 x 4 KB
    __shared__ float tb[NC];
    __shared__ float bsh[RICH * NC];                      // 4.6 KB

    const float* vin = (round == 1) ? g_v0 : g_v01;
    float* Sout = (round == 1) ? g_S1 : g_S2;

    int tid = threadIdx.x;
    int lane = tid & 31;
    int warp = tid >> 5;
    int b = blockIdx.y;
    int i0 = blockIdx.x * RICH;
    int c = tid >> 3;       // owned capsule
    int jj = tid & 7;       // q-segment within capsule

    // loop-invariant v slice -> registers (8 floats)
    float vreg[8];
    {
        float4 v0 = *(const float4*)(vin + b * (NC * QQ) + tid * 8);
        float4 v1 = *(const float4*)(vin + b * (NC * QQ) + tid * 8 + 4);
        vreg[0] = v0.x; vreg[1] = v0.y; vreg[2] = v0.z; vreg[3] = v0.w;
        vreg[4] = v1.x; vreg[5] = v1.y; vreg[6] = v1.z; vreg[7] = v1.w;
    }
    for (int j = tid; j < RICH * NC; j += 256) bsh[j] = bias[i0 * NC + j];

    cp16(hb[0] + tid * 8, g_hat + ((size_t)b * IC + i0) * (NC * QQ) + tid * 8);
    cp_commit();
    cp16(hb[1] + tid * 8, g_hat + ((size_t)b * IC + i0 + 1) * (NC * QQ) + tid * 8);
    cp_commit();

    float racc[8];
#pragma unroll
    for (int j = 0; j < 8; j++) racc[j] = 0.f;

    for (int ii = 0; ii < RICH; ii++) {
        cp_wait<1>();   // tile ii ready (ii+1 may be in flight)
        __syncthreads();
        if (ii + 2 < RICH) {
            int buf = (ii + 2) % 3;
            cp16(hb[buf] + tid * 8,
                 g_hat + ((size_t)b * IC + i0 + ii + 2) * (NC * QQ) + tid * 8);
        }
        cp_commit();

        // single LDS.128: this thread's 8 hat halfs
        uint4 hv = *(const uint4*)(hb[ii % 3] + tid * 8);
        float2 f0 = __half22float2(*(__half2*)&hv.x);
        float2 f1 = __half22float2(*(((__half2*)&hv.x) + 1));
        float2 f2 = __half22float2(*(__half2*)&hv.z);
        float2 f3 = __half22float2(*(((__half2*)&hv.z) + 1));
        float h[8] = {f0.x, f0.y, f1.x, f1.y, f2.x, f2.y, f3.x, f3.y};

        // logits: dot with register v, reduce over 8-thread group
        float s = 0.f;
#pragma unroll
        for (int j = 0; j < 8; j++) s = fmaf(h[j], vreg[j], s);
        s += __shfl_down_sync(0xffffffffu, s, 4);
        s += __shfl_down_sync(0xffffffffu, s, 2);
        s += __shfl_down_sync(0xffffffffu, s, 1);
        if (jj == 0) tb[c] = bsh[ii * NC + c] + s;
        __syncthreads();

        // softmax, redundantly per warp (lane <-> capsule)
        float t = tb[lane];
        float m = t;
#pragma unroll
        for (int o = 16; o > 0; o >>= 1)
            m = fmaxf(m, __shfl_xor_sync(0xffffffffu, m, o));
        float e = __expf(t - m);
        float se = e;
#pragma unroll
        for (int o = 16; o > 0; o >>= 1)
            se += __shfl_xor_sync(0xffffffffu, se, o);
        float w = e / se;

        // weight for own capsule: c = warp*4 + (lane>>3) -> source lane c
        float wc = __shfl_sync(0xffffffffu, w, c & 31);

        // register accumulation
#pragma unroll
        for (int j = 0; j < 8; j++) racc[j] = fmaf(wc, h[j], racc[j]);
    }

    float* sp = Sout + b * (NC * QQ) + tid * 8;
#pragma unroll
    for (int j = 0; j < 8; j++) atomicAdd(sp + j, racc[j]);
}

// ---------------- squash ----------------
// squash0: reduce S0 partials + squash -> v0
__global__ void squash0_kernel() {
    int vec = blockIdx.x;  // b*NC + c
    int lane = threadIdx.x;
    float x0 = 0.f, x1 = 0.f;
#pragma unroll 4
    for (int ib = 0; ib < NIBLK; ib++) {
        x0 += g_S0p[(size_t)ib * SV + vec * QQ + lane];
        x1 += g_S0p[(size_t)ib * SV + vec * QQ + 32 + lane];
    }
    float ss = x0 * x0 + x1 * x1;
#pragma unroll
    for (int o = 16; o > 0; o >>= 1)
        ss += __shfl_xor_sync(0xffffffffu, ss, o);
    float sc = (ss > 0.f) ? (ss / (1.f + ss)) * rsqrtf(ss) : 0.f;
    g_v0[vec * QQ + lane] = sc * x0;
    g_v0[vec * QQ + 32 + lane] = sc * x1;
}

// mode 1: v01 = v0 + squash(S1); mode 2: out = squash(S2)
__global__ void squash_kernel(int mode, float* __restrict__ dout) {
    const float* S = (mode == 1) ? g_S1 : g_S2;
    int vec = blockIdx.x;
    int lane = threadIdx.x;
    float x0 = S[vec * QQ + lane];
    float x1 = S[vec * QQ + 32 + lane];
    float ss = x0 * x0 + x1 * x1;
#pragma unroll
    for (int o = 16; o > 0; o >>= 1)
        ss += __shfl_xor_sync(0xffffffffu, ss, o);
    float sc = (ss > 0.f) ? (ss / (1.f + ss)) * rsqrtf(ss) : 0.f;
    float o0 = sc * x0, o1 = sc * x1;
    if (mode == 1) {
        g_v01[vec * QQ + lane] = g_v0[vec * QQ + lane] + o0;
        g_v01[vec * QQ + 32 + lane] = g_v0[vec * QQ + 32 + lane] + o1;
    } else {
        dout[vec * QQ + lane] = o0;
        dout[vec * QQ + 32 + lane] = o1;
    }
}

// ---------------- launch ----------------
extern "C" void kernel_launch(void* const* d_in, const int* in_sizes, int n_in,
                              void* d_out, int out_size) {
    const float* x = (const float*)d_in[0];     // [32,1152,64]
    const float* W = (const float*)d_in[1];     // [1152,32,64,64]
    const float* bias = (const float*)d_in[2];  // [1,1152,32,1]
    float* out = (float*)d_out;                 // [32,32,64]

    static int smem_set = 0;
    if (!smem_set) {
        cudaFuncSetAttribute(gemm_kernel, cudaFuncAttributeMaxDynamicSharedMemorySize,
                             GEMM_SMEM_BYTES);
        smem_set = 1;
    }

    zero_kernel<<<SV / 256, 256>>>();
    gemm_kernel<<<dim3(NC / 2, NIBLK), 128, GEMM_SMEM_BYTES>>>(x, W, bias);
    squash0_kernel<<<BB * NC, 32>>>();
    route_kernel<<<dim3(IC / RICH, BB), 256>>>(1, bias);
    squash_kernel<<<BB * NC, 32>>>(1, out);
    route_kernel<<<dim3(IC / RICH, BB), 256>>>(2, bias);
    squash_kernel<<<BB * NC, 32>>>(2, out);
}

// round 11
// speedup vs baseline: 1.2417x; 1.1042x over previous
#include <cuda_runtime.h>
#include <cuda_fp16.h>

// CapsuleLayer dynamic routing, GB300 sm_103a.
// B=32, IN_CAPS=1152, P=64, NUM_CAPS=32, Q=64, NUM_ROUTING=3.
//
// hat[b,i,c,q] = sum_p x[b,i,p] * W[i,c,p,q]   (tf32 mma.sync, stored fp16)
// r0: c0 = softmax_c(bias) batch-independent -> S0 partials inside GEMM (fp32)
// r1: b1 = bias + <hat,v0>_q ; S1 = sum_i softmax_c(b1)*hat ; v1=squash(S1)
// r2: b2 = bias + <hat,v0+v1>_q ; S2 = ... ; out = squash(S2)

#define BB 32
#define IC 1152
#define PP 64
#define NC 32
#define QQ 64
#define HAT_ELEMS (BB * IC * NC * QQ)
#define SV (BB * NC * QQ)
#define NIBLK 36

// ---------------- device scratch ----------------
__device__ __align__(16) __half g_hat[HAT_ELEMS];      // 151 MB
__device__ __align__(16) float g_S0p[NIBLK * SV];      // 9.4 MB partials
__device__ __align__(16) float g_S1[SV];
__device__ __align__(16) float g_S2[SV];
__device__ __align__(16) float g_v0[SV];
__device__ __align__(16) float g_v01[SV];

// ---------------- helpers ----------------
__device__ __forceinline__ unsigned int fu(float f) { return __float_as_uint(f); }

__device__ __forceinline__ void cp16(const void* smem_dst, const void* gmem_src) {
    unsigned int s = (unsigned int)__cvta_generic_to_shared(smem_dst);
    asm volatile("cp.async.cg.shared.global [%0], [%1], 16;" :: "r"(s), "l"(gmem_src));
}
__device__ __forceinline__ void cp_commit() {
    asm volatile("cp.async.commit_group;");
}
template <int N>
__device__ __forceinline__ void cp_wait() {
    asm volatile("cp.async.wait_group %0;" :: "n"(N));
}

// tf32 m16n8k8: D += A*B. A row-major [16x8], B col-major [8x8], fp32 accum.
#define MMA_TF32(D, A, B0, B1)                                            \
    asm volatile(                                                          \
        "mma.sync.aligned.m16n8k8.row.col.f32.tf32.tf32.f32 "              \
        "{%0,%1,%2,%3},{%4,%5,%6,%7},{%8,%9},{%0,%1,%2,%3};"               \
        : "+f"((D)[0]), "+f"((D)[1]), "+f"((D)[2]), "+f"((D)[3])           \
        : "r"(fu((A)[0])), "r"(fu((A)[1])), "r"(fu((A)[2])), "r"(fu((A)[3])), \
          "r"(fu(B0)), "r"(fu(B1)))

// ---------------- prep ----------------
__global__ void zero_kernel() {
    int idx = blockIdx.x * blockDim.x + threadIdx.x;
    if (idx < SV) {
        g_S1[idx] = 0.f;
        g_S2[idx] = 0.f;
    }
}

// ---------------- GEMM (tf32): hat (fp16, staged) + S0 partials + fused c0 --
// Grid (16 cpairs, 36 iblocks), 128 threads (4 warps), 2 CTAs/SM.
#define ICH 32
#define WS_STRIDE 136     // 136 % 32 == 8 -> bank = 8k+n : conflict-free B reads
#define XS_STRIDE 68      // 68 % 32 == 4  -> bank = 4b+p : conflict-free A reads
#define HS_STRIDE 136     // halfs per staging row
#define WS_FLOATS (PP * WS_STRIDE)   // 8704
#define XS_FLOATS (BB * XS_STRIDE)   // 2176
#define HS_FLOATS (BB * HS_STRIDE / 2)
#define GEMM_SMEM_BYTES ((2 * WS_FLOATS + 2 * XS_FLOATS + HS_FLOATS) * 4)  // 95744

__device__ __forceinline__ void gemm_prefetch(float* ws, float* xs,
                                              const float* __restrict__ x,
                                              const float* __restrict__ W,
                                              int i, int cpair, int tid) {
    const float4* wsrc = (const float4*)(W + ((size_t)i * NC + cpair * 2) * (PP * QQ));
#pragma unroll
    for (int k = 0; k < 16; k++) {
        int j4 = tid + 128 * k;          // [0,2048)
        int cl = j4 >> 10;
        int p = (j4 >> 4) & 63;
        int q4 = j4 & 15;
        cp16(ws + p * WS_STRIDE + cl * QQ + q4 * 4, wsrc + j4);
    }
#pragma unroll
    for (int k = 0; k < 4; k++) {
        int j = tid + 128 * k;           // [0,512)
        int b = j >> 4;
        int p4 = j & 15;
        cp16(xs + b * XS_STRIDE + p4 * 4, x + ((size_t)b * IC + i) * PP + p4 * 4);
    }
}

__global__ __launch_bounds__(128, 2) void gemm_kernel(const float* __restrict__ x,
                                                      const float* __restrict__ W,
                                                      const float* __restrict__ bias) {
    extern __shared__ __align__(16) float smem[];
    __shared__ float c0sh[ICH][2];
    float* ws0 = smem;
    float* ws1 = smem + WS_FLOATS;
    float* xs0 = smem + 2 * WS_FLOATS;
    float* xs1 = xs0 + XS_FLOATS;
    __half* stag = (__half*)(xs1 + XS_FLOATS);   // [32 rows][136 halfs]

    int tid = threadIdx.x;
    int warp = tid >> 5;
    int lane = tid & 31;
    int g = lane >> 2;      // 0..7
    int tig = lane & 3;     // 0..3
    int cpair = blockIdx.x;
    int iblk = blockIdx.y;
    int i0 = iblk * ICH;
    int n0 = warp * 32;               // slice within 128-wide N
    int cl = warp >> 1;               // capsule-local
    int c = cpair * 2 + cl;
    int qn = n0 & 63;
    int qbase = qn + tig * 2;

    gemm_prefetch(ws0, xs0, x, W, i0, cpair, tid);
    cp_commit();

    // fused c0 = softmax_c(bias) for this CTA's rows (overlaps first loads)
    if (tid < ICH) {
        const float* bp = bias + (size_t)(i0 + tid) * NC;
        float m = -1e30f;
#pragma unroll 8
        for (int cc = 0; cc < NC; cc++) m = fmaxf(m, bp[cc]);
        float s = 0.f;
#pragma unroll 8
        for (int cc = 0; cc < NC; cc++) s += __expf(bp[cc] - m);
        float inv = 1.f / s;
        c0sh[tid][0] = __expf(bp[cpair * 2 + 0] - m) * inv;
        c0sh[tid][1] = __expf(bp[cpair * 2 + 1] - m) * inv;
    }

    float s0[2][4][4];
#pragma unroll
    for (int mt = 0; mt < 2; mt++)
#pragma unroll
        for (int nt = 0; nt < 4; nt++)
#pragma unroll
            for (int j = 0; j < 4; j++) s0[mt][nt][j] = 0.f;

    for (int ii = 0; ii < ICH; ii++) {
        int i = i0 + ii;
        cp_wait<0>();
        __syncthreads();
        if (ii + 1 < ICH) {
            float* wsn = ((ii + 1) & 1) ? ws1 : ws0;
            float* xsn = ((ii + 1) & 1) ? xs1 : xs0;
            gemm_prefetch(wsn, xsn, x, W, i + 1, cpair, tid);
        }
        cp_commit();
        const float* wsc = (ii & 1) ? ws1 : ws0;
        const float* xsc = (ii & 1) ? xs1 : xs0;

        float d[2][4][4];
#pragma unroll
        for (int mt = 0; mt < 2; mt++)
#pragma unroll
            for (int nt = 0; nt < 4; nt++)
#pragma unroll
                for (int j = 0; j < 4; j++) d[mt][nt][j] = 0.f;

#pragma unroll
        for (int ks = 0; ks < 8; ks++) {
            float a[2][4];
#pragma unroll
            for (int mt = 0; mt < 2; mt++) {
                int base = (mt * 16 + g) * XS_STRIDE + ks * 8 + tig;
                a[mt][0] = xsc[base];
                a[mt][1] = xsc[base + 8 * XS_STRIDE];
                a[mt][2] = xsc[base + 4];
                a[mt][3] = xsc[base + 8 * XS_STRIDE + 4];
            }
#pragma unroll
            for (int nt = 0; nt < 4; nt++) {
                int bb = (ks * 8 + tig) * WS_STRIDE + n0 + nt * 8 + g;
                float b0 = wsc[bb];
                float b1 = wsc[bb + 4 * WS_STRIDE];
                MMA_TF32(d[0][nt], a[0], b0, b1);
                MMA_TF32(d[1][nt], a[1], b0, b1);
            }
        }

        // S0 fused accumulation + stage hat tile in smem (conflict-free STS)
        float wgt = c0sh[ii][cl];
#pragma unroll
        for (int mt = 0; mt < 2; mt++) {
#pragma unroll
            for (int nt = 0; nt < 4; nt++) {
                int row0 = mt * 16 + g;
                int ncol = n0 + nt * 8 + tig * 2;
                *(__half2*)(stag + row0 * HS_STRIDE + ncol) =
                    __floats2half2_rn(d[mt][nt][0], d[mt][nt][1]);
                *(__half2*)(stag + (row0 + 8) * HS_STRIDE + ncol) =
                    __floats2half2_rn(d[mt][nt][2], d[mt][nt][3]);
#pragma unroll
                for (int j = 0; j < 4; j++)
                    s0[mt][nt][j] = fmaf(wgt, d[mt][nt][j], s0[mt][nt][j]);
            }
        }
        __syncthreads();

        // coalesced writeback: staging row b (n 0..127) -> 256B contiguous gmem
        {
            int c16 = lane & 15;
            int rsub = lane >> 4;
#pragma unroll
            for (int k = 0; k < 4; k++) {
                int r = warp * 8 + k * 2 + rsub;
                uint4 v = *(const uint4*)(stag + r * HS_STRIDE + c16 * 8);
                __half* dst = g_hat + (((size_t)r * IC + i) * NC + cpair * 2) * QQ
                              + c16 * 8;
                *(uint4*)dst = v;
            }
        }
    }

    // non-atomic per-iblock S0 partials
    float* sp = g_S0p + (size_t)iblk * SV;
#pragma unroll
    for (int mt = 0; mt < 2; mt++) {
#pragma unroll
        for (int nt = 0; nt < 4; nt++) {
            int q = qbase + nt * 8;
            int b0r = mt * 16 + g;
            *(float2*)(sp + ((size_t)b0r * NC + c) * QQ + q) =
                make_float2(s0[mt][nt][0], s0[mt][nt][1]);
            *(float2*)(sp + ((size_t)(b0r + 8) * NC + c) * QQ + q) =
                make_float2(s0[mt][nt][2], s0[mt][nt][3]);
        }
    }
}

// ---------------- routing pass (rounds 1, 2) -------------------------------
// Group-of-4 phase batching. Thread (c=tid>>3, jj=tid&7) owns hat [c*64+jj*8,+8).
// Per 4-tile group: 1 cp_wait + 2 barriers; softmax computed once per tile
// (warp w<4 handles tile w); hat converted once, floats kept in registers.
#define RICH 36
#define IIB 4
#define NGRP (RICH / IIB)

__global__ __launch_bounds__(256) void route_kernel(int round,
                                                    const float* __restrict__ bias) {
    __shared__ __align__(16) __half hb[2][IIB][NC * QQ];  // 32 KB
    __shared__ float tb[IIB * NC];
    __shared__ float csh[IIB * NC];
    __shared__ float bsh[RICH * NC];                      // 4.6 KB

    const float* vin = (round == 1) ? g_v0 : g_v01;
    float* Sout = (round == 1) ? g_S1 : g_S2;

    int tid = threadIdx.x;
    int lane = tid & 31;
    int warp = tid >> 5;
    int b = blockIdx.y;
    int i0 = blockIdx.x * RICH;
    int c = tid >> 3;       // owned capsule
    int jj = tid & 7;       // q-segment within capsule

    // loop-invariant v slice -> registers (8 floats)
    float vreg[8];
    *(float4*)&vreg[0] = *(const float4*)(vin + b * (NC * QQ) + tid * 8);
    *(float4*)&vreg[4] = *(const float4*)(vin + b * (NC * QQ) + tid * 8 + 4);

    for (int j = tid; j < RICH * NC; j += 256) bsh[j] = bias[i0 * NC + j];

    // prefetch group 0
#pragma unroll
    for (int t = 0; t < IIB; t++)
        cp16(hb[0][t] + tid * 8,
             g_hat + ((size_t)b * IC + i0 + t) * (NC * QQ) + tid * 8);
    cp_commit();

    float racc[8];
#pragma unroll
    for (int j = 0; j < 8; j++) racc[j] = 0.f;

    int buf = 0;
    for (int gg = 0; gg < NGRP; gg++) {
        cp_wait<0>();
        __syncthreads();
        if (gg + 1 < NGRP) {
            int ib = i0 + (gg + 1) * IIB;
#pragma unroll
            for (int t = 0; t < IIB; t++)
                cp16(hb[buf ^ 1][t] + tid * 8,
                     g_hat + ((size_t)b * IC + ib + t) * (NC * QQ) + tid * 8);
        }
        cp_commit();

        // phase 1: load + convert once, logits for 4 tiles (ILP across tiles)
        float hf[IIB][8];
#pragma unroll
        for (int t = 0; t < IIB; t++) {
            uint4 hv = *(const uint4*)(hb[buf][t] + tid * 8);
            float2 f0 = __half22float2(*(__half2*)&hv.x);
            float2 f1 = __half22float2(*(((__half2*)&hv.x) + 1));
            float2 f2 = __half22float2(*(__half2*)&hv.z);
            float2 f3 = __half22float2(*(((__half2*)&hv.z) + 1));
            hf[t][0] = f0.x; hf[t][1] = f0.y; hf[t][2] = f1.x; hf[t][3] = f1.y;
            hf[t][4] = f2.x; hf[t][5] = f2.y; hf[t][6] = f3.x; hf[t][7] = f3.y;
        }
#pragma unroll
        for (int t = 0; t < IIB; t++) {
            float s = 0.f;
#pragma unroll
            for (int j = 0; j < 8; j++) s = fmaf(hf[t][j], vreg[j], s);
            s += __shfl_down_sync(0xffffffffu, s, 4);
            s += __shfl_down_sync(0xffffffffu, s, 2);
            s += __shfl_down_sync(0xffffffffu, s, 1);
            if (jj == 0) tb[t * NC + c] = bsh[(gg * IIB + t) * NC + c] + s;
        }
        __syncthreads();

        // phase 2: warp w < 4 -> softmax of tile w (lane <-> capsule)
        if (warp < IIB) {
            float t_ = tb[warp * NC + lane];
            float m = t_;
#pragma unroll
            for (int o = 16; o > 0; o >>= 1)
                m = fmaxf(m, __shfl_xor_sync(0xffffffffu, m, o));
            float e = __expf(t_ - m);
            float se = e;
#pragma unroll
            for (int o = 16; o > 0; o >>= 1)
                se += __shfl_xor_sync(0xffffffffu, se, o);
            csh[warp * NC + lane] = e / se;
        }
        __syncthreads();

        // phase 3: weighted accumulation (csh read is an 8-thread broadcast)
#pragma unroll
        for (int t = 0; t < IIB; t++) {
            float wc = csh[t * NC + c];
#pragma unroll
            for (int j = 0; j < 8; j++) racc[j] = fmaf(wc, hf[t][j], racc[j]);
        }
        buf ^= 1;
    }

    float* sp = Sout + b * (NC * QQ) + tid * 8;
#pragma unroll
    for (int j = 0; j < 8; j++) atomicAdd(sp + j, racc[j]);
}

// ---------------- squash ----------------
// squash0: reduce S0 partials + squash -> v0
__global__ void squash0_kernel() {
    int vec = blockIdx.x;  // b*NC + c
    int lane = threadIdx.x;
    float x0 = 0.f, x1 = 0.f;
#pragma unroll 4
    for (int ib = 0; ib < NIBLK; ib++) {
        x0 += g_S0p[(size_t)ib * SV + vec * QQ + lane];
        x1 += g_S0p[(size_t)ib * SV + vec * QQ + 32 + lane];
    }
    float ss = x0 * x0 + x1 * x1;
#pragma unroll
    for (int o = 16; o > 0; o >>= 1)
        ss += __shfl_xor_sync(0xffffffffu, ss, o);
    float sc = (ss > 0.f) ? (ss / (1.f + ss)) * rsqrtf(ss) : 0.f;
    g_v0[vec * QQ + lane] = sc * x0;
    g_v0[vec * QQ + 32 + lane] = sc * x1;
}

// mode 1: v01 = v0 + squash(S1); mode 2: out = squash(S2)
__global__ void squash_kernel(int mode, float* __restrict__ dout) {
    const float* S = (mode == 1) ? g_S1 : g_S2;
    int vec = blockIdx.x;
    int lane = threadIdx.x;
    float x0 = S[vec * QQ + lane];
    float x1 = S[vec * QQ + 32 + lane];
    float ss = x0 * x0 + x1 * x1;
#pragma unroll
    for (int o = 16; o > 0; o >>= 1)
        ss += __shfl_xor_sync(0xffffffffu, ss, o);
    float sc = (ss > 0.f) ? (ss / (1.f + ss)) * rsqrtf(ss) : 0.f;
    float o0 = sc * x0, o1 = sc * x1;
    if (mode == 1) {
        g_v01[vec * QQ + lane] = g_v0[vec * QQ + lane] + o0;
        g_v01[vec * QQ + 32 + lane] = g_v0[vec * QQ + 32 + lane] + o1;
    } else {
        dout[vec * QQ + lane] = o0;
        dout[vec * QQ + 32 + lane] = o1;
    }
}

// ---------------- launch ----------------
extern "C" void kernel_launch(void* const* d_in, const int* in_sizes, int n_in,
                              void* d_out, int out_size) {
    const float* x = (const float*)d_in[0];     // [32,1152,64]
    const float* W = (const float*)d_in[1];     // [1152,32,64,64]
    const float* bias = (const float*)d_in[2];  // [1,1152,32,1]
    float* out = (float*)d_out;                 // [32,32,64]

    static int smem_set = 0;
    if (!smem_set) {
        cudaFuncSetAttribute(gemm_kernel, cudaFuncAttributeMaxDynamicSharedMemorySize,
                             GEMM_SMEM_BYTES);
        smem_set = 1;
    }

    zero_kernel<<<SV / 256, 256>>>();
    gemm_kernel<<<dim3(NC / 2, NIBLK), 128, GEMM_SMEM_BYTES>>>(x, W, bias);
    squash0_kernel<<<BB * NC, 32>>>();
    route_kernel<<<dim3(IC / RICH, BB), 256>>>(1, bias);
    squash_kernel<<<BB * NC, 32>>>(1, out);
    route_kernel<<<dim3(IC / RICH, BB), 256>>>(2, bias);
    squash_kernel<<<BB * NC, 32>>>(2, out);
}

// round 12
// speedup vs baseline: 1.3008x; 1.0476x over previous
#include <cuda_runtime.h>
#include <cuda_fp16.h>

// CapsuleLayer dynamic routing, GB300 sm_103a.
// B=32, IN_CAPS=1152, P=64, NUM_CAPS=32, Q=64, NUM_ROUTING=3.
//
// hat[b,i,c,q] = sum_p x[b,i,p] * W[i,c,p,q]   (tf32 mma.sync, stored fp16)
// r0: c0 = softmax_c(bias) batch-independent -> S0 partials inside GEMM (fp32)
// r1: b1 = bias + <hat,v0>_q ; S1 = sum_i softmax_c(b1)*hat ; v1=squash(S1)
// r2: b2 = bias + <hat,v0+v1>_q ; S2 = ... ; out = squash(S2)

#define BB 32
#define IC 1152
#define PP 64
#define NC 32
#define QQ 64
#define HAT_ELEMS (BB * IC * NC * QQ)
#define SV (BB * NC * QQ)
#define NIBLK 36

// ---------------- device scratch ----------------
__device__ __align__(16) __half g_hat[HAT_ELEMS];      // 151 MB
__device__ __align__(16) float g_S0p[NIBLK * SV];      // 9.4 MB partials
__device__ __align__(16) float g_S1[SV];
__device__ __align__(16) float g_S2[SV];
__device__ __align__(16) float g_v0[SV];
__device__ __align__(16) float g_v01[SV];

// ---------------- helpers ----------------
__device__ __forceinline__ unsigned int fu(float f) { return __float_as_uint(f); }

__device__ __forceinline__ void cp16(const void* smem_dst, const void* gmem_src) {
    unsigned int s = (unsigned int)__cvta_generic_to_shared(smem_dst);
    asm volatile("cp.async.cg.shared.global [%0], [%1], 16;" :: "r"(s), "l"(gmem_src));
}
__device__ __forceinline__ void cp_commit() {
    asm volatile("cp.async.commit_group;");
}
template <int N>
__device__ __forceinline__ void cp_wait() {
    asm volatile("cp.async.wait_group %0;" :: "n"(N));
}

// tf32 m16n8k8: D += A*B. A row-major [16x8], B col-major [8x8], fp32 accum.
#define MMA_TF32(D, A, B0, B1)                                            \
    asm volatile(                                                          \
        "mma.sync.aligned.m16n8k8.row.col.f32.tf32.tf32.f32 "              \
        "{%0,%1,%2,%3},{%4,%5,%6,%7},{%8,%9},{%0,%1,%2,%3};"               \
        : "+f"((D)[0]), "+f"((D)[1]), "+f"((D)[2]), "+f"((D)[3])           \
        : "r"(fu((A)[0])), "r"(fu((A)[1])), "r"(fu((A)[2])), "r"(fu((A)[3])), \
          "r"(fu(B0)), "r"(fu(B1)))

// ---------------- prep ----------------
__global__ void zero_kernel() {
    int idx = blockIdx.x * blockDim.x + threadIdx.x;
    if (idx < SV) {
        g_S1[idx] = 0.f;
        g_S2[idx] = 0.f;
    }
}

// ---------------- GEMM (tf32): hat (fp16, staged) + S0 partials + fused c0 --
// Grid (16 cpairs, 36 iblocks), 128 threads (4 warps), 2 CTAs/SM.
#define ICH 32
#define WS_STRIDE 136     // 136 % 32 == 8 -> bank = 8k+n : conflict-free B reads
#define XS_STRIDE 68      // 68 % 32 == 4  -> bank = 4b+p : conflict-free A reads
#define HS_STRIDE 136     // halfs per staging row
#define WS_FLOATS (PP * WS_STRIDE)   // 8704
#define XS_FLOATS (BB * XS_STRIDE)   // 2176
#define HS_FLOATS (BB * HS_STRIDE / 2)
#define GEMM_SMEM_BYTES ((2 * WS_FLOATS + 2 * XS_FLOATS + HS_FLOATS) * 4)  // 95744

__device__ __forceinline__ void gemm_prefetch(float* ws, float* xs,
                                              const float* __restrict__ x,
                                              const float* __restrict__ W,
                                              int i, int cpair, int tid) {
    const float4* wsrc = (const float4*)(W + ((size_t)i * NC + cpair * 2) * (PP * QQ));
#pragma unroll
    for (int k = 0; k < 16; k++) {
        int j4 = tid + 128 * k;          // [0,2048)
        int cl = j4 >> 10;
        int p = (j4 >> 4) & 63;
        int q4 = j4 & 15;
        cp16(ws + p * WS_STRIDE + cl * QQ + q4 * 4, wsrc + j4);
    }
#pragma unroll
    for (int k = 0; k < 4; k++) {
        int j = tid + 128 * k;           // [0,512)
        int b = j >> 4;
        int p4 = j & 15;
        cp16(xs + b * XS_STRIDE + p4 * 4, x + ((size_t)b * IC + i) * PP + p4 * 4);
    }
}

__global__ __launch_bounds__(128, 2) void gemm_kernel(const float* __restrict__ x,
                                                      const float* __restrict__ W,
                                                      const float* __restrict__ bias) {
    extern __shared__ __align__(16) float smem[];
    __shared__ float c0sh[ICH][2];
    float* ws0 = smem;
    float* ws1 = smem + WS_FLOATS;
    float* xs0 = smem + 2 * WS_FLOATS;
    float* xs1 = xs0 + XS_FLOATS;
    __half* stag = (__half*)(xs1 + XS_FLOATS);   // [32 rows][136 halfs]

    int tid = threadIdx.x;
    int warp = tid >> 5;
    int lane = tid & 31;
    int g = lane >> 2;      // 0..7
    int tig = lane & 3;     // 0..3
    int cpair = blockIdx.x;
    int iblk = blockIdx.y;
    int i0 = iblk * ICH;
    int n0 = warp * 32;               // slice within 128-wide N
    int cl = warp >> 1;               // capsule-local
    int c = cpair * 2 + cl;
    int qn = n0 & 63;
    int qbase = qn + tig * 2;

    gemm_prefetch(ws0, xs0, x, W, i0, cpair, tid);
    cp_commit();

    // fused c0 = softmax_c(bias) for this CTA's rows (overlaps first loads)
    if (tid < ICH) {
        const float* bp = bias + (size_t)(i0 + tid) * NC;
        float m = -1e30f;
#pragma unroll 8
        for (int cc = 0; cc < NC; cc++) m = fmaxf(m, bp[cc]);
        float s = 0.f;
#pragma unroll 8
        for (int cc = 0; cc < NC; cc++) s += __expf(bp[cc] - m);
        float inv = 1.f / s;
        c0sh[tid][0] = __expf(bp[cpair * 2 + 0] - m) * inv;
        c0sh[tid][1] = __expf(bp[cpair * 2 + 1] - m) * inv;
    }

    float s0[2][4][4];
#pragma unroll
    for (int mt = 0; mt < 2; mt++)
#pragma unroll
        for (int nt = 0; nt < 4; nt++)
#pragma unroll
            for (int j = 0; j < 4; j++) s0[mt][nt][j] = 0.f;

    for (int ii = 0; ii < ICH; ii++) {
        int i = i0 + ii;
        cp_wait<0>();
        __syncthreads();
        if (ii + 1 < ICH) {
            float* wsn = ((ii + 1) & 1) ? ws1 : ws0;
            float* xsn = ((ii + 1) & 1) ? xs1 : xs0;
            gemm_prefetch(wsn, xsn, x, W, i + 1, cpair, tid);
        }
        cp_commit();
        const float* wsc = (ii & 1) ? ws1 : ws0;
        const float* xsc = (ii & 1) ? xs1 : xs0;

        float d[2][4][4];
#pragma unroll
        for (int mt = 0; mt < 2; mt++)
#pragma unroll
            for (int nt = 0; nt < 4; nt++)
#pragma unroll
                for (int j = 0; j < 4; j++) d[mt][nt][j] = 0.f;

#pragma unroll
        for (int ks = 0; ks < 8; ks++) {
            float a[2][4];
#pragma unroll
            for (int mt = 0; mt < 2; mt++) {
                int base = (mt * 16 + g) * XS_STRIDE + ks * 8 + tig;
                a[mt][0] = xsc[base];
                a[mt][1] = xsc[base + 8 * XS_STRIDE];
                a[mt][2] = xsc[base + 4];
                a[mt][3] = xsc[base + 8 * XS_STRIDE + 4];
            }
#pragma unroll
            for (int nt = 0; nt < 4; nt++) {
                int bb = (ks * 8 + tig) * WS_STRIDE + n0 + nt * 8 + g;
                float b0 = wsc[bb];
                float b1 = wsc[bb + 4 * WS_STRIDE];
                MMA_TF32(d[0][nt], a[0], b0, b1);
                MMA_TF32(d[1][nt], a[1], b0, b1);
            }
        }

        // S0 fused accumulation + stage hat tile in smem (conflict-free STS)
        float wgt = c0sh[ii][cl];
#pragma unroll
        for (int mt = 0; mt < 2; mt++) {
#pragma unroll
            for (int nt = 0; nt < 4; nt++) {
                int row0 = mt * 16 + g;
                int ncol = n0 + nt * 8 + tig * 2;
                *(__half2*)(stag + row0 * HS_STRIDE + ncol) =
                    __floats2half2_rn(d[mt][nt][0], d[mt][nt][1]);
                *(__half2*)(stag + (row0 + 8) * HS_STRIDE + ncol) =
                    __floats2half2_rn(d[mt][nt][2], d[mt][nt][3]);
#pragma unroll
                for (int j = 0; j < 4; j++)
                    s0[mt][nt][j] = fmaf(wgt, d[mt][nt][j], s0[mt][nt][j]);
            }
        }
        __syncthreads();

        // coalesced writeback: staging row b (n 0..127) -> 256B contiguous gmem
        {
            int c16 = lane & 15;
            int rsub = lane >> 4;
#pragma unroll
            for (int k = 0; k < 4; k++) {
                int r = warp * 8 + k * 2 + rsub;
                uint4 v = *(const uint4*)(stag + r * HS_STRIDE + c16 * 8);
                __half* dst = g_hat + (((size_t)r * IC + i) * NC + cpair * 2) * QQ
                              + c16 * 8;
                *(uint4*)dst = v;
            }
        }
    }

    // non-atomic per-iblock S0 partials
    float* sp = g_S0p + (size_t)iblk * SV;
#pragma unroll
    for (int mt = 0; mt < 2; mt++) {
#pragma unroll
        for (int nt = 0; nt < 4; nt++) {
            int q = qbase + nt * 8;
            int b0r = mt * 16 + g;
            *(float2*)(sp + ((size_t)b0r * NC + c) * QQ + q) =
                make_float2(s0[mt][nt][0], s0[mt][nt][1]);
            *(float2*)(sp + ((size_t)(b0r + 8) * NC + c) * QQ + q) =
                make_float2(s0[mt][nt][2], s0[mt][nt][3]);
        }
    }
}

// ---------------- routing pass (rounds 1, 2) -------------------------------
// Group-of-4 tiles, 3-stage cp.async pipeline (wait<1>: 2 groups in flight).
// Thread (c=tid>>3, jj=tid&7) owns hat [c*64+jj*8, +8). hat kept as packed
// half2 registers (uint4/tile), converted on use. 4 CTAs/SM.
#define RICH 36
#define IIB 4
#define NGRP (RICH / IIB)
#define RT_GRP_HALFS (IIB * NC * QQ)               // 8192 halfs = 16 KB
#define RT_SMEM_BYTES (3 * RT_GRP_HALFS * 2 + RICH * NC * 4 + 2 * IIB * NC * 4)

__global__ __launch_bounds__(256, 4) void route_kernel(int round,
                                                       const float* __restrict__ bias) {
    extern __shared__ __align__(16) char rsm[];
    __half* hb = (__half*)rsm;                              // 3 x 16 KB
    float* bsh = (float*)(rsm + 3 * RT_GRP_HALFS * 2);      // RICH*NC
    float* tb = bsh + RICH * NC;                            // IIB*NC
    float* csh = tb + IIB * NC;                             // IIB*NC

    const float* vin = (round == 1) ? g_v0 : g_v01;
    float* Sout = (round == 1) ? g_S1 : g_S2;

    int tid = threadIdx.x;
    int lane = tid & 31;
    int warp = tid >> 5;
    int b = blockIdx.y;
    int i0 = blockIdx.x * RICH;
    int c = tid >> 3;       // owned capsule
    int jj = tid & 7;       // q-segment within capsule

    // loop-invariant v slice -> registers (8 floats)
    float vreg[8];
    *(float4*)&vreg[0] = *(const float4*)(vin + b * (NC * QQ) + tid * 8);
    *(float4*)&vreg[4] = *(const float4*)(vin + b * (NC * QQ) + tid * 8 + 4);

    for (int j = tid; j < RICH * NC; j += 256) bsh[j] = bias[i0 * NC + j];

    // prefetch groups 0 and 1 (separate commit groups)
#pragma unroll
    for (int t = 0; t < IIB; t++)
        cp16(hb + 0 * RT_GRP_HALFS + t * (NC * QQ) + tid * 8,
             g_hat + ((size_t)b * IC + i0 + t) * (NC * QQ) + tid * 8);
    cp_commit();
#pragma unroll
    for (int t = 0; t < IIB; t++)
        cp16(hb + 1 * RT_GRP_HALFS + t * (NC * QQ) + tid * 8,
             g_hat + ((size_t)b * IC + i0 + IIB + t) * (NC * QQ) + tid * 8);
    cp_commit();

    float racc[8];
#pragma unroll
    for (int j = 0; j < 8; j++) racc[j] = 0.f;

    for (int gg = 0; gg < NGRP; gg++) {
        cp_wait<1>();   // group gg ready; gg+1 may still be in flight
        __syncthreads();
        if (gg + 2 < NGRP) {
            int ib = i0 + (gg + 2) * IIB;
            __half* dst = hb + ((gg + 2) % 3) * RT_GRP_HALFS;
#pragma unroll
            for (int t = 0; t < IIB; t++)
                cp16(dst + t * (NC * QQ) + tid * 8,
                     g_hat + ((size_t)b * IC + ib + t) * (NC * QQ) + tid * 8);
        }
        cp_commit();    // empty group at tail keeps wait<1> semantics

        const __half* hbuf = hb + (gg % 3) * RT_GRP_HALFS;

        // phase 1: single LDS.128 per tile, packed half2 regs; logits
        uint4 hv[IIB];
#pragma unroll
        for (int t = 0; t < IIB; t++)
            hv[t] = *(const uint4*)(hbuf + t * (NC * QQ) + tid * 8);
#pragma unroll
        for (int t = 0; t < IIB; t++) {
            const __half2* hp = (const __half2*)&hv[t];
            float s = 0.f;
#pragma unroll
            for (int j = 0; j < 4; j++) {
                float2 f = __half22float2(hp[j]);
                s = fmaf(f.x, vreg[2 * j], s);
                s = fmaf(f.y, vreg[2 * j + 1], s);
            }
            s += __shfl_down_sync(0xffffffffu, s, 4);
            s += __shfl_down_sync(0xffffffffu, s, 2);
            s += __shfl_down_sync(0xffffffffu, s, 1);
            if (jj == 0) tb[t * NC + c] = bsh[(gg * IIB + t) * NC + c] + s;
        }
        __syncthreads();

        // phase 2: warp w < 4 -> softmax of tile w (lane <-> capsule)
        if (warp < IIB) {
            float t_ = tb[warp * NC + lane];
            float m = t_;
#pragma unroll
            for (int o = 16; o > 0; o >>= 1)
                m = fmaxf(m, __shfl_xor_sync(0xffffffffu, m, o));
            float e = __expf(t_ - m);
            float se = e;
#pragma unroll
            for (int o = 16; o > 0; o >>= 1)
                se += __shfl_xor_sync(0xffffffffu, se, o);
            csh[warp * NC + lane] = e / se;
        }
        __syncthreads();

        // phase 3: weighted accumulation (csh read is an 8-thread broadcast)
#pragma unroll
        for (int t = 0; t < IIB; t++) {
            float wc = csh[t * NC + c];
            const __half2* hp = (const __half2*)&hv[t];
#pragma unroll
            for (int j = 0; j < 4; j++) {
                float2 f = __half22float2(hp[j]);
                racc[2 * j] = fmaf(wc, f.x, racc[2 * j]);
                racc[2 * j + 1] = fmaf(wc, f.y, racc[2 * j + 1]);
            }
        }
    }

    float* sp = Sout + b * (NC * QQ) + tid * 8;
#pragma unroll
    for (int j = 0; j < 8; j++) atomicAdd(sp + j, racc[j]);
}

// ---------------- squash ----------------
// squash0: reduce S0 partials + squash -> v0
__global__ void squash0_kernel() {
    int vec = blockIdx.x;  // b*NC + c
    int lane = threadIdx.x;
    float x0 = 0.f, x1 = 0.f;
#pragma unroll 4
    for (int ib = 0; ib < NIBLK; ib++) {
        x0 += g_S0p[(size_t)ib * SV + vec * QQ + lane];
        x1 += g_S0p[(size_t)ib * SV + vec * QQ + 32 + lane];
    }
    float ss = x0 * x0 + x1 * x1;
#pragma unroll
    for (int o = 16; o > 0; o >>= 1)
        ss += __shfl_xor_sync(0xffffffffu, ss, o);
    float sc = (ss > 0.f) ? (ss / (1.f + ss)) * rsqrtf(ss) : 0.f;
    g_v0[vec * QQ + lane] = sc * x0;
    g_v0[vec * QQ + 32 + lane] = sc * x1;
}

// mode 1: v01 = v0 + squash(S1); mode 2: out = squash(S2)
__global__ void squash_kernel(int mode, float* __restrict__ dout) {
    const float* S = (mode == 1) ? g_S1 : g_S2;
    int vec = blockIdx.x;
    int lane = threadIdx.x;
    float x0 = S[vec * QQ + lane];
    float x1 = S[vec * QQ + 32 + lane];
    float ss = x0 * x0 + x1 * x1;
#pragma unroll
    for (int o = 16; o > 0; o >>= 1)
        ss += __shfl_xor_sync(0xffffffffu, ss, o);
    float sc = (ss > 0.f) ? (ss / (1.f + ss)) * rsqrtf(ss) : 0.f;
    float o0 = sc * x0, o1 = sc * x1;
    if (mode == 1) {
        g_v01[vec * QQ + lane] = g_v0[vec * QQ + lane] + o0;
        g_v01[vec * QQ + 32 + lane] = g_v0[vec * QQ + 32 + lane] + o1;
    } else {
        dout[vec * QQ + lane] = o0;
        dout[vec * QQ + 32 + lane] = o1;
    }
}

// ---------------- launch ----------------
extern "C" void kernel_launch(void* const* d_in, const int* in_sizes, int n_in,
                              void* d_out, int out_size) {
    const float* x = (const float*)d_in[0];     // [32,1152,64]
    const float* W = (const float*)d_in[1];     // [1152,32,64,64]
    const float* bias = (const float*)d_in[2];  // [1,1152,32,1]
    float* out = (float*)d_out;                 // [32,32,64]

    static int smem_set = 0;
    if (!smem_set) {
        cudaFuncSetAttribute(gemm_kernel, cudaFuncAttributeMaxDynamicSharedMemorySize,
                             GEMM_SMEM_BYTES);
        cudaFuncSetAttribute(route_kernel, cudaFuncAttributeMaxDynamicSharedMemorySize,
                             RT_SMEM_BYTES);
        smem_set = 1;
    }

    zero_kernel<<<SV / 256, 256>>>();
    gemm_kernel<<<dim3(NC / 2, NIBLK), 128, GEMM_SMEM_BYTES>>>(x, W, bias);
    squash0_kernel<<<BB * NC, 32>>>();
    route_kernel<<<dim3(IC / RICH, BB), 256, RT_SMEM_BYTES>>>(1, bias);
    squash_kernel<<<BB * NC, 32>>>(1, out);
    route_kernel<<<dim3(IC / RICH, BB), 256, RT_SMEM_BYTES>>>(2, bias);
    squash_kernel<<<BB * NC, 32>>>(2, out);
}